// round 2
// baseline (speedup 1.0000x reference)
#include <cuda_runtime.h>
#include <math.h>

#define EPS_BN 1e-5f
#define EPS_LN 1e-5f

#define NQ   1024
#define NSUP 24
#define NTOT 1048

// ---------------------------------------------------------------------------
// Device-global scratch (no allocations anywhere)
// ---------------------------------------------------------------------------
static __device__ float g_convbuf[429260800];  // max: 1048*64*80*80 (L1 conv out)
static __device__ float g_bufA[107315200];     // 1048*64*40*40
static __device__ float g_bufB[26828800];      // 1048*64*20*20
static __device__ float g_stats[512];          // (group,oc) -> {sum, sumsq}
static __device__ float g_scale[256];          // (group,oc)
static __device__ float g_shift[256];
static __device__ float g_wt[112320];          // transposed weights, all layers
static __device__ float g_emb[NTOT * 64];
static __device__ float g_sn[3 * 64];

#define WT1 0
#define WT2 1728
#define WT3 38592
#define WT4 75456

__device__ __forceinline__ int bn_group(int n) {
    return (n < NQ) ? 0 : (1 + ((n - NQ) >> 3));
}

// ---------------------------------------------------------------------------
// Weight transpose: [oc][ic][3][3] -> [ic][k][oc]
// ---------------------------------------------------------------------------
__global__ void tw_k(const float* __restrict__ w, int CIN, int off) {
    int idx = blockIdx.x * 256 + threadIdx.x;
    int tot = CIN * 9 * 64;
    if (idx >= tot) return;
    int oc = idx & 63;
    int kk = (idx >> 6) % 9;
    int ic = idx / (9 * 64);
    g_wt[off + idx] = w[(oc * CIN + ic) * 9 + kk];
}

__global__ void zstats_k() {
    g_stats[threadIdx.x] = 0.f;
}

// ---------------------------------------------------------------------------
// Direct conv 3x3 pad1 + fused BN-stat reduction.
// Block: 256 threads = 4 oc-groups x 64 pixels (8x8 tile). 16 oc/thread.
// Writes conv output to g_convbuf, atomically accumulates per-(group,oc)
// sum/sumsq via warp-shfl + smem combine.
// ---------------------------------------------------------------------------
template <int L>
__global__ void __launch_bounds__(256, 2)
conv_k(const float* __restrict__ in1, const float* __restrict__ in2) {
    constexpr int CIN  = (L == 1) ? 3 : 64;
    constexpr int H    = (L == 1) ? 80 : (L == 2) ? 40 : (L == 3) ? 20 : 10;
    constexpr int ICC  = (L == 1) ? 3 : 8;
    constexpr int TH   = 8, TW = 8;
    constexpr int SR   = TH + 2, SC = TW + 2;
    constexpr int WOFF = (L == 1) ? WT1 : (L == 2) ? WT2 : (L == 3) ? WT3 : WT4;
    constexpr int TILESX = (H + TW - 1) / TW;

    __shared__ float s_in[ICC * SR * SC];
    __shared__ float s_w[ICC * 9 * 64];
    __shared__ float s_red[8][32];

    const int n    = blockIdx.y;
    const int tile = blockIdx.x;
    const int y0   = (tile / TILESX) * TH;
    const int x0   = (tile % TILESX) * TW;
    const int tid  = threadIdx.x;
    const int ocg  = tid >> 6;
    const int pix  = tid & 63;
    const int py   = pix >> 3;
    const int px   = pix & 7;

    const float* gin;
    if constexpr (L == 1) {
        gin = (n < NQ) ? in1 + (size_t)n * (3 * 80 * 80)
                       : in2 + (size_t)(n - NQ) * (3 * 80 * 80);
    } else if constexpr (L == 2) {
        gin = g_bufA + (size_t)n * (64 * 40 * 40);
    } else if constexpr (L == 3) {
        gin = g_bufB + (size_t)n * (64 * 20 * 20);
    } else {
        gin = g_bufA + (size_t)n * (64 * 10 * 10);
    }

    float acc[16];
#pragma unroll
    for (int j = 0; j < 16; j++) acc[j] = 0.f;

    for (int ic0 = 0; ic0 < CIN; ic0 += ICC) {
        // load input chunk (zero-padded halo)
        for (int idx = tid; idx < ICC * SR * SC; idx += 256) {
            int c   = idx % SC;
            int r   = (idx / SC) % SR;
            int icl = idx / (SC * SR);
            int gy = y0 + r - 1, gx = x0 + c - 1;
            float v = 0.f;
            if (gy >= 0 && gy < H && gx >= 0 && gx < H)
                v = gin[((size_t)(ic0 + icl) * H + gy) * H + gx];
            s_in[idx] = v;
        }
        // load weight chunk (already transposed: [ic][k][oc])
        for (int idx = tid; idx < ICC * 9 * 64; idx += 256)
            s_w[idx] = g_wt[WOFF + ic0 * 9 * 64 + idx];
        __syncthreads();

#pragma unroll
        for (int icl = 0; icl < ICC; icl++) {
#pragma unroll
            for (int kk = 0; kk < 9; kk++) {
                int ky = kk / 3, kx = kk % 3;
                float v = s_in[(icl * SR + py + ky) * SC + px + kx];
                const float4* wp = reinterpret_cast<const float4*>(
                    &s_w[(icl * 9 + kk) * 64 + ocg * 16]);
                float4 w0 = wp[0], w1 = wp[1], w2 = wp[2], w3 = wp[3];
                acc[0]  += v * w0.x; acc[1]  += v * w0.y;
                acc[2]  += v * w0.z; acc[3]  += v * w0.w;
                acc[4]  += v * w1.x; acc[5]  += v * w1.y;
                acc[6]  += v * w1.z; acc[7]  += v * w1.w;
                acc[8]  += v * w2.x; acc[9]  += v * w2.y;
                acc[10] += v * w2.z; acc[11] += v * w2.w;
                acc[12] += v * w3.x; acc[13] += v * w3.y;
                acc[14] += v * w3.z; acc[15] += v * w3.w;
            }
        }
        __syncthreads();
    }

    const bool valid = (y0 + py) < H && (x0 + px) < H;
    const int g = bn_group(n);
    float* cb = g_convbuf + (size_t)n * 64 * H * H;

#pragma unroll
    for (int j = 0; j < 16; j++) {
        float v = valid ? acc[j] : 0.f;
        if (valid)
            cb[((ocg * 16 + j) * H + (y0 + py)) * H + (x0 + px)] = v;
        float s = v, q = v * v;
#pragma unroll
        for (int o = 16; o > 0; o >>= 1) {
            s += __shfl_down_sync(0xffffffffu, s, o);
            q += __shfl_down_sync(0xffffffffu, q, o);
        }
        if ((tid & 31) == 0) {
            s_red[tid >> 5][j]      = s;
            s_red[tid >> 5][16 + j] = q;
        }
    }
    __syncthreads();
    if (tid < 128) {
        int gg = tid >> 5;   // ocg
        int j  = tid & 31;   // 0..15 sum, 16..31 sumsq
        float v = s_red[2 * gg][j] + s_red[2 * gg + 1][j];
        int oc = gg * 16 + (j & 15);
        atomicAdd(&g_stats[(g * 64 + oc) * 2 + (j >> 4)], v);
    }
}

// ---------------------------------------------------------------------------
// BN finalize: stats -> per-(group,oc) scale/shift
// ---------------------------------------------------------------------------
__global__ void finalize_k(const float* __restrict__ gam,
                           const float* __restrict__ bet, int H) {
    int t   = threadIdx.x;          // 256 = 4 groups x 64 oc
    int grp = t >> 6, oc = t & 63;
    float cnt = (grp == 0 ? (float)NQ : 8.f) * (float)(H * H);
    float s = g_stats[t * 2], q = g_stats[t * 2 + 1];
    float m = s / cnt;
    float v = q / cnt - m * m;
    float sc = gam[oc] * rsqrtf(v + EPS_BN);
    g_scale[t] = sc;
    g_shift[t] = bet[oc] - m * sc;
}

// ---------------------------------------------------------------------------
// BN apply + LeakyReLU(0.2) + maxpool2
// ---------------------------------------------------------------------------
template <int L>
__global__ void bnpool_k() {
    constexpr int H  = (L == 1) ? 80 : (L == 2) ? 40 : (L == 3) ? 20 : 10;
    constexpr int Wp = H / 2;
    const int total  = NTOT * 64 * Wp * Wp;
    int idx = blockIdx.x * 256 + threadIdx.x;
    if (idx >= total) return;

    int px = idx % Wp;
    int t  = idx / Wp;
    int py = t % Wp; t /= Wp;
    int oc = t & 63;
    int n  = t >> 6;
    int g  = bn_group(n);
    float sc = g_scale[g * 64 + oc];
    float sh = g_shift[g * 64 + oc];

    const float* p = g_convbuf + (((size_t)n * 64 + oc) * H + 2 * py) * H + 2 * px;
    float a = p[0], b = p[1], c = p[H], d = p[H + 1];
    a = fmaf(a, sc, sh); a = a > 0.f ? a : 0.2f * a;
    b = fmaf(b, sc, sh); b = b > 0.f ? b : 0.2f * b;
    c = fmaf(c, sc, sh); c = c > 0.f ? c : 0.2f * c;
    d = fmaf(d, sc, sh); d = d > 0.f ? d : 0.2f * d;
    float m = fmaxf(fmaxf(a, b), fmaxf(c, d));

    float* out;
    if constexpr (L == 1)      out = g_bufA;
    else if constexpr (L == 2) out = g_bufB;
    else if constexpr (L == 3) out = g_bufA;
    else                       out = g_bufB;
    out[idx] = m;
}

// ---------------------------------------------------------------------------
// Embedding: maxpool5 over [n][oc][5][5] -> g_emb[n][oc]
// ---------------------------------------------------------------------------
__global__ void embed_k() {
    int idx = blockIdx.x * 256 + threadIdx.x;
    if (idx >= NTOT * 64) return;
    const float* p = g_bufB + (size_t)idx * 25;
    float m = p[0];
#pragma unroll
    for (int i = 1; i < 25; i++) m = fmaxf(m, p[i]);
    g_emb[idx] = m;
}

// ---------------------------------------------------------------------------
// Prototype attention + layernorm + row-normalize -> g_sn[3][64]
// Single block, 64 threads.
// ---------------------------------------------------------------------------
__global__ void attn_k(const float* __restrict__ wq, const float* __restrict__ wk,
                       const float* __restrict__ wv, const float* __restrict__ fcw,
                       const float* __restrict__ fcb, const float* __restrict__ lng,
                       const float* __restrict__ lnb) {
    __shared__ float P[3][64], Q[3][64], K[3][64], V[3][64], O[3][64];
    __shared__ float A[3][3], MU[3], SG[3], NR[3];
    int t = threadIdx.x;  // 0..63

    for (int l = 0; l < 3; l++) {
        float s = 0.f;
        for (int i = 0; i < 8; i++) s += g_emb[(NQ + l * 8 + i) * 64 + t];
        P[l][t] = s * 0.125f;
    }
    __syncthreads();

    for (int l = 0; l < 3; l++) {
        float q = 0.f, k = 0.f, v = 0.f;
        for (int d = 0; d < 64; d++) {
            float p = P[l][d];
            q += p * wq[t * 64 + d];
            k += p * wk[t * 64 + d];
            v += p * wv[t * 64 + d];
        }
        Q[l][t] = q; K[l][t] = k; V[l][t] = v;
    }
    __syncthreads();

    if (t < 9) {
        int qi = t / 3, ki = t % 3;
        float a = 0.f;
        for (int d = 0; d < 64; d++) a += Q[qi][d] * K[ki][d];
        A[qi][ki] = a * 0.125f;  // 1/sqrt(64)
    }
    __syncthreads();
    if (t < 3) {
        float m = fmaxf(A[t][0], fmaxf(A[t][1], A[t][2]));
        float e0 = expf(A[t][0] - m), e1 = expf(A[t][1] - m), e2 = expf(A[t][2] - m);
        float inv = 1.f / (e0 + e1 + e2);
        A[t][0] = e0 * inv; A[t][1] = e1 * inv; A[t][2] = e2 * inv;
    }
    __syncthreads();

    for (int l = 0; l < 3; l++)
        O[l][t] = A[l][0] * V[0][t] + A[l][1] * V[1][t] + A[l][2] * V[2][t];
    __syncthreads();

    for (int l = 0; l < 3; l++) {
        float o = fcb[t];
        for (int d = 0; d < 64; d++) o += O[l][d] * fcw[t * 64 + d];
        Q[l][t] = o + P[l][t];  // residual, reuse Q
    }
    __syncthreads();

    if (t < 3) {
        float s = 0.f, q = 0.f;
        for (int d = 0; d < 64; d++) { float x = Q[t][d]; s += x; q += x * x; }
        float m = s / 64.f;
        MU[t] = m;
        SG[t] = rsqrtf(q / 64.f - m * m + EPS_LN);
    }
    __syncthreads();

    for (int l = 0; l < 3; l++)
        K[l][t] = (Q[l][t] - MU[l]) * SG[l] * lng[t] + lnb[t];  // reuse K
    __syncthreads();

    if (t < 3) {
        float q = 0.f;
        for (int d = 0; d < 64; d++) q += K[t][d] * K[t][d];
        NR[t] = rsqrtf(q);
    }
    __syncthreads();

    for (int l = 0; l < 3; l++)
        g_sn[l * 64 + t] = K[l][t] * NR[l];
}

// ---------------------------------------------------------------------------
// Cosine similarity: out[n][k] = (emb[n]/||emb[n]||) . sn[k]
// One warp per query row.
// ---------------------------------------------------------------------------
__global__ void cos_k(float* __restrict__ out) {
    int warp = threadIdx.x >> 5, lane = threadIdx.x & 31;
    int n = blockIdx.x * 4 + warp;
    if (n >= NQ) return;
    float v1 = g_emb[n * 64 + lane];
    float v2 = g_emb[n * 64 + 32 + lane];
    float ss = v1 * v1 + v2 * v2;
#pragma unroll
    for (int o = 16; o > 0; o >>= 1) ss += __shfl_xor_sync(0xffffffffu, ss, o);
    float rn = rsqrtf(ss);
#pragma unroll
    for (int k = 0; k < 3; k++) {
        float d = v1 * g_sn[k * 64 + lane] + v2 * g_sn[k * 64 + 32 + lane];
#pragma unroll
        for (int o = 16; o > 0; o >>= 1) d += __shfl_xor_sync(0xffffffffu, d, o);
        if (lane == 0) out[n * 3 + k] = d * rn;
    }
}

// ---------------------------------------------------------------------------
// Launch
// ---------------------------------------------------------------------------
extern "C" void kernel_launch(void* const* d_in, const int* in_sizes, int n_in,
                              void* d_out, int out_size) {
    const float* input1  = (const float*)d_in[0];
    const float* input2  = (const float*)d_in[1];
    const float* conv1_w = (const float*)d_in[2];
    const float* conv2_w = (const float*)d_in[3];
    const float* conv3_w = (const float*)d_in[4];
    const float* conv4_w = (const float*)d_in[5];
    const float* bn_g[4] = {(const float*)d_in[6], (const float*)d_in[8],
                            (const float*)d_in[10], (const float*)d_in[12]};
    const float* bn_b[4] = {(const float*)d_in[7], (const float*)d_in[9],
                            (const float*)d_in[11], (const float*)d_in[13]};
    const float* wq   = (const float*)d_in[14];
    const float* wk   = (const float*)d_in[15];
    const float* wv   = (const float*)d_in[16];
    const float* fc_w = (const float*)d_in[17];
    const float* fc_b = (const float*)d_in[18];
    const float* ln_g = (const float*)d_in[19];
    const float* ln_b = (const float*)d_in[20];
    float* out = (float*)d_out;

    // weight transpose
    tw_k<<<(3 * 9 * 64 + 255) / 256, 256>>>(conv1_w, 3, WT1);
    tw_k<<<(64 * 9 * 64 + 255) / 256, 256>>>(conv2_w, 64, WT2);
    tw_k<<<(64 * 9 * 64 + 255) / 256, 256>>>(conv3_w, 64, WT3);
    tw_k<<<(64 * 9 * 64 + 255) / 256, 256>>>(conv4_w, 64, WT4);

    // Layer 1: 80x80 -> pool 40x40
    zstats_k<<<1, 512>>>();
    conv_k<1><<<dim3(100, NTOT), 256>>>(input1, input2);
    finalize_k<<<1, 256>>>(bn_g[0], bn_b[0], 80);
    { int tot = NTOT * 64 * 40 * 40; bnpool_k<1><<<(tot + 255) / 256, 256>>>(); }

    // Layer 2: 40x40 -> pool 20x20
    zstats_k<<<1, 512>>>();
    conv_k<2><<<dim3(25, NTOT), 256>>>(nullptr, nullptr);
    finalize_k<<<1, 256>>>(bn_g[1], bn_b[1], 40);
    { int tot = NTOT * 64 * 20 * 20; bnpool_k<2><<<(tot + 255) / 256, 256>>>(); }

    // Layer 3: 20x20 -> pool 10x10
    zstats_k<<<1, 512>>>();
    conv_k<3><<<dim3(9, NTOT), 256>>>(nullptr, nullptr);
    finalize_k<<<1, 256>>>(bn_g[2], bn_b[2], 20);
    { int tot = NTOT * 64 * 10 * 10; bnpool_k<3><<<(tot + 255) / 256, 256>>>(); }

    // Layer 4: 10x10 -> pool 5x5
    zstats_k<<<1, 512>>>();
    conv_k<4><<<dim3(4, NTOT), 256>>>(nullptr, nullptr);
    finalize_k<<<1, 256>>>(bn_g[3], bn_b[3], 10);
    { int tot = NTOT * 64 * 5 * 5; bnpool_k<4><<<(tot + 255) / 256, 256>>>(); }

    // embedding (maxpool5)
    embed_k<<<(NTOT * 64 + 255) / 256, 256>>>();

    // prototype attention + LN + normalize
    attn_k<<<1, 64>>>(wq, wk, wv, fc_w, fc_b, ln_g, ln_b);

    // cosine similarity -> [1024, 3]
    cos_k<<<256, 128>>>(out);
}